// round 13
// baseline (speedup 1.0000x reference)
#include <cuda_runtime.h>
#include <cuda_bf16.h>
#include <cstdint>

#define B_ROWS 65536
#define D_IN   256
#define D_G    512
#define EPS_BN 1e-5f

// scratch for z = GBN(feat@W^T) * priors
__device__ float g_z[(size_t)B_ROWS * D_G];
// per-row-block completion counters (zero-initialized at module load; each
// row-block's last CTA resets its counter to 0 -> graph replays see zeros)
__device__ int g_cnt[B_ROWS / 128];

// ---------------------------------------------------------------------------
// helpers: ldmatrix / mma.sync (plain compute_103-legal PTX)
// ---------------------------------------------------------------------------
__device__ __forceinline__ uint32_t smem_u32_of(const void* p) {
    uint32_t a;
    asm("{ .reg .u64 t; cvta.to.shared.u64 t, %1; cvt.u32.u64 %0, t; }" : "=r"(a) : "l"(p));
    return a;
}

__device__ __forceinline__ void ldsm_x4(uint32_t* r, uint32_t addr) {
    asm volatile("ldmatrix.sync.aligned.m8n8.x4.shared.b16 {%0,%1,%2,%3}, [%4];"
                 : "=r"(r[0]), "=r"(r[1]), "=r"(r[2]), "=r"(r[3]) : "r"(addr));
}
__device__ __forceinline__ void ldsm_x2(uint32_t* r, uint32_t addr) {
    asm volatile("ldmatrix.sync.aligned.m8n8.x2.shared.b16 {%0,%1}, [%2];"
                 : "=r"(r[0]), "=r"(r[1]) : "r"(addr));
}
__device__ __forceinline__ void mma16816(float* d, const uint32_t* a, const uint32_t* b) {
    asm volatile("mma.sync.aligned.m16n8k16.row.col.f32.bf16.bf16.f32 "
                 "{%0,%1,%2,%3}, {%4,%5,%6,%7}, {%8,%9}, {%0,%1,%2,%3};"
                 : "+f"(d[0]), "+f"(d[1]), "+f"(d[2]), "+f"(d[3])
                 : "r"(a[0]), "r"(a[1]), "r"(a[2]), "r"(a[3]), "r"(b[0]), "r"(b[1]));
}

// smem tile geometry: 128 rows x 32 bf16 cols, padded row stride 80 bytes
#define ROWB   80
#define TILE_B (128 * ROWB)       // 10240 bytes per tile
#define STAGE_B (4 * TILE_B)      // Ahi, Alo, Bhi, Blo = 40960
#define SMEM_TOTAL (2 * STAGE_B)  // 81920

// ---------------------------------------------------------------------------
// Fused kernel: bf16 3-term-split MMA GEMM (C = feat @ W^T) + GhostBN +
// priors -> z, then the LAST CTA of each 128-row block runs sparsemax for
// the whole block (z tiles are L2-hot).
// Grid (D_G/128, B/128) = (4, 512), 256 threads (8 warps, 2x4 warp grid).
// ---------------------------------------------------------------------------
__global__ __launch_bounds__(256, 1)
void gemm_gbn_spmax(const float* __restrict__ feat,
                    const float* __restrict__ W,
                    const float* __restrict__ priors,
                    const float* __restrict__ gamma,
                    const float* __restrict__ beta,
                    float* __restrict__ outp)
{
    extern __shared__ char smem[];
    __shared__ int s_last;
    const uint32_t sbase = smem_u32_of(smem);

    const int tid  = threadIdx.x;
    const int wid  = tid >> 5;
    const int lane = tid & 31;
    const int warp_m = wid >> 2;    // 0..1 -> 64-row stripe
    const int warp_n = wid & 3;     // 0..3 -> 32-col stripe
    const int m0 = blockIdx.y * 128;
    const int n0 = blockIdx.x * 128;

    // ---- loader mapping: row = tid>>1 (0..127), colhalf = (tid&1)*16 ----
    const int lrow = tid >> 1;
    const int lcol = (tid & 1) * 16;
    const float* aptr = feat + (size_t)(m0 + lrow) * D_IN + lcol;
    const float* bptr = W    + (size_t)(n0 + lrow) * D_IN + lcol;
    const uint32_t st_off = (uint32_t)(lrow * ROWB + lcol * 2);   // bf16 = 2B

    float acc[4][4][4];
#pragma unroll
    for (int f = 0; f < 4; f++)
#pragma unroll
        for (int g = 0; g < 4; g++)
#pragma unroll
            for (int r = 0; r < 4; r++) acc[f][g][r] = 0.0f;

    float4 ra[4], rb[4];
#pragma unroll
    for (int j = 0; j < 4; j++) {
        ra[j] = *(const float4*)(aptr + j * 4);
        rb[j] = *(const float4*)(bptr + j * 4);
    }

    // per-thread LDSM base coords
    const uint32_t a_r = (uint32_t)(warp_m * 64 + (lane & 15));
    const uint32_t a_c = (uint32_t)((lane >> 4) * 8);
    const uint32_t b_r = (uint32_t)(warp_n * 32 + (lane & 7));
    const uint32_t b_c = (uint32_t)(((lane >> 3) & 1) * 8);

    const int NCHUNK = D_IN / 32;   // 8

    auto cvst = [&](uint32_t dstbase, const float4* v) {
#pragma unroll
        for (int j = 0; j < 4; j++) {
            float4 a = v[j];
            __nv_bfloat162 h0 = __float22bfloat162_rn(make_float2(a.x, a.y));
            __nv_bfloat162 h1 = __float22bfloat162_rn(make_float2(a.z, a.w));
            __nv_bfloat162 l0 = __float22bfloat162_rn(make_float2(
                a.x - __bfloat162float(h0.x), a.y - __bfloat162float(h0.y)));
            __nv_bfloat162 l1 = __float22bfloat162_rn(make_float2(
                a.z - __bfloat162float(h1.x), a.w - __bfloat162float(h1.y)));
            uint2 uh, ul;
            uh.x = *(uint32_t*)&h0; uh.y = *(uint32_t*)&h1;
            ul.x = *(uint32_t*)&l0; ul.y = *(uint32_t*)&l1;
            *(uint2*)(smem + (dstbase + st_off + j * 8))          = uh;
            *(uint2*)(smem + (dstbase + st_off + j * 8) + TILE_B) = ul;
        }
    };

    // initial chunk -> stage 0
    cvst(0u,           ra);
    cvst(2u * TILE_B,  rb);
    __syncthreads();

    for (int t = 0; t < NCHUNK; ++t) {
        // prefetch next chunk into regs
        if (t + 1 < NCHUNK) {
            const float* ap = aptr + (t + 1) * 32;
            const float* bp = bptr + (t + 1) * 32;
#pragma unroll
            for (int j = 0; j < 4; j++) {
                ra[j] = *(const float4*)(ap + j * 4);
                rb[j] = *(const float4*)(bp + j * 4);
            }
        }

        // ---- MMAs over stage t&1 ----
        const uint32_t stg = sbase + (uint32_t)(t & 1) * STAGE_B;
        const uint32_t Ahi = stg, Alo = stg + TILE_B;
        const uint32_t Bhi = stg + 2 * TILE_B, Blo = stg + 3 * TILE_B;

#pragma unroll
        for (int s = 0; s < 2; ++s) {            // two k16 steps per chunk
            const uint32_t k0 = (uint32_t)(s * 16);
            uint32_t bh[4][2], bl[4][2];
#pragma unroll
            for (int g = 0; g < 4; ++g) {
                const uint32_t boff = (b_r + g * 8) * ROWB + (k0 + b_c) * 2;
                ldsm_x2(bh[g], Bhi + boff);
                ldsm_x2(bl[g], Blo + boff);
            }
#pragma unroll
            for (int f = 0; f < 4; ++f) {
                const uint32_t aoff = (a_r + f * 16) * ROWB + (k0 + a_c) * 2;
                uint32_t ah[4], al[4];
                ldsm_x4(ah, Ahi + aoff);
                ldsm_x4(al, Alo + aoff);
#pragma unroll
                for (int g = 0; g < 4; ++g) {
                    mma16816(acc[f][g], ah, bh[g]);   // hi*hi
                    mma16816(acc[f][g], ah, bl[g]);   // hi*lo
                    mma16816(acc[f][g], al, bh[g]);   // lo*hi
                }
            }
        }

        // ---- store next chunk into the other stage ----
        if (t + 1 < NCHUNK) {
            const uint32_t nb = (uint32_t)((t + 1) & 1) * STAGE_B;
            cvst(nb,               ra);
            cvst(nb + 2 * TILE_B,  rb);
        }
        __syncthreads();
    }

    // ---------------- GhostBN epilogue ----------------
    float* Psum   = (float*)smem;
    float* Psq    = (float*)(smem + 8192);
    float* cscale = (float*)(smem + 16384);
    float* cshift = (float*)(smem + 16896);

    const int prow = warp_m * 8 + (lane >> 2);          // 0..15
    const int cbase = warp_n * 32 + (lane & 3) * 2;     // even col of this lane

#pragma unroll
    for (int g = 0; g < 4; ++g) {
        float se = 0.f, so = 0.f, qe = 0.f, qo = 0.f;
#pragma unroll
        for (int f = 0; f < 4; ++f) {
            const float e0 = acc[f][g][0], e1 = acc[f][g][2];
            const float o0 = acc[f][g][1], o1 = acc[f][g][3];
            se += e0 + e1;  qe += e0 * e0 + e1 * e1;
            so += o0 + o1;  qo += o0 * o0 + o1 * o1;
        }
        Psum[prow * 128 + cbase + g * 8]     = se;
        Psum[prow * 128 + cbase + g * 8 + 1] = so;
        Psq [prow * 128 + cbase + g * 8]     = qe;
        Psq [prow * 128 + cbase + g * 8 + 1] = qo;
    }
    __syncthreads();

    if (tid < 128) {
        float s = 0.f, s2 = 0.f;
#pragma unroll
        for (int r = 0; r < 16; r++) {
            s  += Psum[r * 128 + tid];
            s2 += Psq [r * 128 + tid];
        }
        const float mean = s * (1.0f / 128.0f);
        const float var  = s2 * (1.0f / 128.0f) - mean * mean;
        const float sc   = gamma[n0 + tid] * rsqrtf(var + EPS_BN);
        cscale[tid] = sc;
        cshift[tid] = beta[n0 + tid] - mean * sc;
    }
    __syncthreads();

#pragma unroll
    for (int g = 0; g < 4; ++g) {
        const int cl = cbase + g * 8;
        const float2 sc = *(const float2*)&cscale[cl];
        const float2 sh = *(const float2*)&cshift[cl];
        const int col = n0 + cl;
#pragma unroll
        for (int f = 0; f < 4; ++f) {
            const int row0 = m0 + warp_m * 64 + f * 16 + (lane >> 2);
#pragma unroll
            for (int h = 0; h < 2; ++h) {
                const size_t row = (size_t)(row0 + h * 8);
                const float2 p = *(const float2*)&priors[row * D_G + col];
                float2 z;
                z.x = fmaf(acc[f][g][h * 2 + 0], sc.x, sh.x) * p.x;
                z.y = fmaf(acc[f][g][h * 2 + 1], sc.y, sh.y) * p.y;
                *(float2*)&g_z[row * D_G + col] = z;
            }
        }
    }

    // ---------------- completion counter: last CTA runs sparsemax ----------
    __threadfence();                        // release this CTA's z stores
    __syncthreads();
    if (tid == 0)
        s_last = (atomicAdd(&g_cnt[blockIdx.y], 1) == 3);
    __syncthreads();

    if (s_last) {
        __threadfence();                    // acquire the other CTAs' z stores

        // 8 warps x 16 rows; per row: warp-Michelot sparsemax (z is L2-hot)
        const int rbase = m0 + wid * 16;
        for (int i = 0; i < 16; ++i) {
            const size_t row = (size_t)(rbase + i);
            const float4* zr = (const float4*)(g_z + row * D_G);

            float4 v[4];
#pragma unroll
            for (int c = 0; c < 4; c++) v[c] = zr[c * 32 + lane];

            float mx = fmaxf(fmaxf(v[0].x, v[0].y), fmaxf(v[0].z, v[0].w));
#pragma unroll
            for (int c = 1; c < 4; c++)
                mx = fmaxf(mx, fmaxf(fmaxf(v[c].x, v[c].y), fmaxf(v[c].z, v[c].w)));
#pragma unroll
            for (int o = 16; o > 0; o >>= 1)
                mx = fmaxf(mx, __shfl_xor_sync(0xffffffffu, mx, o));

            float s = 0.0f;
#pragma unroll
            for (int c = 0; c < 4; c++) {
                v[c].x -= mx; v[c].y -= mx; v[c].z -= mx; v[c].w -= mx;
                s += (v[c].x + v[c].y) + (v[c].z + v[c].w);
            }
#pragma unroll
            for (int o = 16; o > 0; o >>= 1)
                s += __shfl_xor_sync(0xffffffffu, s, o);

            float tau = (s - 1.0f) * (1.0f / 512.0f);

            for (int it = 0; it < 64; ++it) {
                float ns = 0.0f;
                unsigned k = 0;
#pragma unroll
                for (int c = 0; c < 4; c++) {
                    if (v[c].x > tau) { ns += v[c].x; k++; }
                    if (v[c].y > tau) { ns += v[c].y; k++; }
                    if (v[c].z > tau) { ns += v[c].z; k++; }
                    if (v[c].w > tau) { ns += v[c].w; k++; }
                }
#pragma unroll
                for (int o = 16; o > 0; o >>= 1)
                    ns += __shfl_xor_sync(0xffffffffu, ns, o);
                k = __reduce_add_sync(0xffffffffu, k);

                const float nt = (ns - 1.0f) / (float)k;
                if (nt == tau) break;
                tau = nt;
            }

            float4* orow = (float4*)(outp + row * D_G);
#pragma unroll
            for (int c = 0; c < 4; c++) {
                float4 r;
                r.x = fmaxf(v[c].x - tau, 0.0f);
                r.y = fmaxf(v[c].y - tau, 0.0f);
                r.z = fmaxf(v[c].z - tau, 0.0f);
                r.w = fmaxf(v[c].w - tau, 0.0f);
                orow[c * 32 + lane] = r;
            }
        }

        // reset counter for the next graph replay
        if (tid == 0) g_cnt[blockIdx.y] = 0;
    }
}

// ---------------------------------------------------------------------------
extern "C" void kernel_launch(void* const* d_in, const int* in_sizes, int n_in,
                              void* d_out, int out_size)
{
    const float* priors = (const float*)d_in[0];   // [B, 512]
    const float* feat   = (const float*)d_in[1];   // [B, 256]
    const float* W      = (const float*)d_in[2];   // [512, 256]
    const float* gamma  = (const float*)d_in[3];   // [512]
    const float* beta   = (const float*)d_in[4];   // [512]
    float* out = (float*)d_out;                    // [B, 512]

    cudaFuncSetAttribute(gemm_gbn_spmax,
                         cudaFuncAttributeMaxDynamicSharedMemorySize, SMEM_TOTAL);

    dim3 grid(D_G / 128, B_ROWS / 128);            // (4, 512)
    gemm_gbn_spmax<<<grid, 256, SMEM_TOTAL>>>(feat, W, priors, gamma, beta, out);
}

// round 15
// speedup vs baseline: 1.4736x; 1.4736x over previous
#include <cuda_runtime.h>
#include <cuda_bf16.h>
#include <cstdint>

#define B_ROWS 65536
#define D_IN   256
#define D_G    512
#define EPS_BN 1e-5f

// scratch for z = GBN(feat@W^T) * priors
__device__ float g_z[(size_t)B_ROWS * D_G];

// ---------------------------------------------------------------------------
// helpers: ldmatrix / mma.sync (plain compute_103-legal PTX)
// ---------------------------------------------------------------------------
__device__ __forceinline__ uint32_t smem_u32_of(const void* p) {
    uint32_t a;
    asm("{ .reg .u64 t; cvta.to.shared.u64 t, %1; cvt.u32.u64 %0, t; }" : "=r"(a) : "l"(p));
    return a;
}

__device__ __forceinline__ void ldsm_x4(uint32_t* r, uint32_t addr) {
    asm volatile("ldmatrix.sync.aligned.m8n8.x4.shared.b16 {%0,%1,%2,%3}, [%4];"
                 : "=r"(r[0]), "=r"(r[1]), "=r"(r[2]), "=r"(r[3]) : "r"(addr));
}
__device__ __forceinline__ void mma16816(float* d, const uint32_t* a, const uint32_t* b) {
    asm volatile("mma.sync.aligned.m16n8k16.row.col.f32.bf16.bf16.f32 "
                 "{%0,%1,%2,%3}, {%4,%5,%6,%7}, {%8,%9}, {%0,%1,%2,%3};"
                 : "+f"(d[0]), "+f"(d[1]), "+f"(d[2]), "+f"(d[3])
                 : "r"(a[0]), "r"(a[1]), "r"(a[2]), "r"(a[3]), "r"(b[0]), "r"(b[1]));
}

// smem tile geometry: 128 rows x 32 bf16 cols, padded row stride 80 bytes
// (16B aligned; 8 consecutive rows hit 8 distinct 16B bank groups -> LDSM
//  conflict-free)
#define ROWB   80
#define TILE_B (128 * ROWB)       // 10240 bytes per tile
#define STAGE_B (4 * TILE_B)      // Ahi, Alo, Bhi, Blo = 40960
#define SMEM_TOTAL (2 * STAGE_B)  // 81920

// ---------------------------------------------------------------------------
// Kernel 1: bf16 3-term-split MMA GEMM (C = feat @ W^T) + GhostBN + priors
// Grid (D_G/128, B/128) = (4, 512), 512 threads = 16 warps (4m x 4n grid),
// warp tile 32x32. launch_bounds(512,1): 128-reg cap -> no spills, 16
// resident warps/SM to hide LDSM/MMA/convert latency.
// ---------------------------------------------------------------------------
__global__ __launch_bounds__(512, 1)
void gemm_gbn_mma(const float* __restrict__ feat,
                  const float* __restrict__ W,
                  const float* __restrict__ priors,
                  const float* __restrict__ gamma,
                  const float* __restrict__ beta)
{
    extern __shared__ char smem[];
    const uint32_t sbase = smem_u32_of(smem);

    const int tid  = threadIdx.x;
    const int wid  = tid >> 5;      // 0..15
    const int lane = tid & 31;
    const int warp_m = wid >> 2;    // 0..3 -> 32-row stripe
    const int warp_n = wid & 3;     // 0..3 -> 32-col stripe
    const int m0 = blockIdx.y * 128;
    const int n0 = blockIdx.x * 128;

    // ---- loader mapping: row = tid>>2 (0..127), 8 cols = 2 float4 ----
    const int lrow = tid >> 2;
    const int lcol = (tid & 3) * 8;
    const float* aptr = feat + (size_t)(m0 + lrow) * D_IN + lcol;
    const float* bptr = W    + (size_t)(n0 + lrow) * D_IN + lcol;
    const uint32_t st_off = (uint32_t)(lrow * ROWB + lcol * 2);   // bf16 = 2B

    float acc[2][4][4];
#pragma unroll
    for (int f = 0; f < 2; f++)
#pragma unroll
        for (int g = 0; g < 4; g++)
#pragma unroll
            for (int r = 0; r < 4; r++) acc[f][g][r] = 0.0f;

    float4 ra[2], rb[2];
#pragma unroll
    for (int j = 0; j < 2; j++) {
        ra[j] = *(const float4*)(aptr + j * 4);
        rb[j] = *(const float4*)(bptr + j * 4);
    }

    // per-thread LDSM coords
    // A (x4): rows warp_m*32 + f*16 + (lane&15), col group (lane>>4)*8
    const uint32_t a_r = (uint32_t)(warp_m * 32 + (lane & 15));
    const uint32_t a_c = (uint32_t)((lane >> 4) * 8);
    // B (x4, 2 n-frags per load): mat=lane>>3 -> (n-frag pair, k col group)
    const uint32_t b_row = (uint32_t)(warp_n * 32 + (lane >> 4) * 8 + (lane & 7));
    const uint32_t b_kc  = (uint32_t)(((lane >> 3) & 1) * 8);

    const int NCHUNK = D_IN / 32;   // 8

    auto cvst = [&](uint32_t dstbase, const float4* v) {
#pragma unroll
        for (int j = 0; j < 2; j++) {
            float4 a = v[j];
            __nv_bfloat162 h0 = __float22bfloat162_rn(make_float2(a.x, a.y));
            __nv_bfloat162 h1 = __float22bfloat162_rn(make_float2(a.z, a.w));
            __nv_bfloat162 l0 = __float22bfloat162_rn(make_float2(
                a.x - __bfloat162float(h0.x), a.y - __bfloat162float(h0.y)));
            __nv_bfloat162 l1 = __float22bfloat162_rn(make_float2(
                a.z - __bfloat162float(h1.x), a.w - __bfloat162float(h1.y)));
            uint2 uh, ul;
            uh.x = *(uint32_t*)&h0; uh.y = *(uint32_t*)&h1;
            ul.x = *(uint32_t*)&l0; ul.y = *(uint32_t*)&l1;
            *(uint2*)(smem + (dstbase + st_off + j * 8))          = uh;
            *(uint2*)(smem + (dstbase + st_off + j * 8) + TILE_B) = ul;
        }
    };

    // initial chunk -> stage 0
    cvst(0u,           ra);
    cvst(2u * TILE_B,  rb);
    __syncthreads();

    for (int t = 0; t < NCHUNK; ++t) {
        // prefetch next chunk into regs
        if (t + 1 < NCHUNK) {
            const float* ap = aptr + (t + 1) * 32;
            const float* bp = bptr + (t + 1) * 32;
#pragma unroll
            for (int j = 0; j < 2; j++) {
                ra[j] = *(const float4*)(ap + j * 4);
                rb[j] = *(const float4*)(bp + j * 4);
            }
        }

        // ---- MMAs over stage t&1 ----
        const uint32_t stg = sbase + (uint32_t)(t & 1) * STAGE_B;
        const uint32_t Ahi = stg, Alo = stg + TILE_B;
        const uint32_t Bhi = stg + 2 * TILE_B, Blo = stg + 3 * TILE_B;

#pragma unroll
        for (int s = 0; s < 2; ++s) {            // two k16 steps per chunk
            const uint32_t k0 = (uint32_t)(s * 16);
            uint32_t bh[2][4], bl[2][4];
#pragma unroll
            for (int gp = 0; gp < 2; ++gp) {
                const uint32_t boff = (b_row + gp * 16) * ROWB + (k0 + b_kc) * 2;
                ldsm_x4(bh[gp], Bhi + boff);
                ldsm_x4(bl[gp], Blo + boff);
            }
#pragma unroll
            for (int f = 0; f < 2; ++f) {
                const uint32_t aoff = (a_r + f * 16) * ROWB + (k0 + a_c) * 2;
                uint32_t ah[4], al[4];
                ldsm_x4(ah, Ahi + aoff);
                ldsm_x4(al, Alo + aoff);
#pragma unroll
                for (int g = 0; g < 4; ++g) {
                    const uint32_t* bhp = &bh[g >> 1][(g & 1) * 2];
                    const uint32_t* blp = &bl[g >> 1][(g & 1) * 2];
                    mma16816(acc[f][g], ah, bhp);   // hi*hi
                    mma16816(acc[f][g], ah, blp);   // hi*lo
                    mma16816(acc[f][g], al, bhp);   // lo*hi
                }
            }
        }

        // ---- store next chunk into the other stage ----
        if (t + 1 < NCHUNK) {
            const uint32_t nb = (uint32_t)((t + 1) & 1) * STAGE_B;
            cvst(nb,               ra);
            cvst(nb + 2 * TILE_B,  rb);
        }
        __syncthreads();
    }

    // ---------------- GhostBN epilogue ----------------
    // Psum[32][128] @0 (16KB), Psq @16384, cscale @32768, cshift @33280
    float* Psum   = (float*)smem;
    float* Psq    = (float*)(smem + 16384);
    float* cscale = (float*)(smem + 32768);
    float* cshift = (float*)(smem + 33280);

    const int prow  = warp_m * 8 + (lane >> 2);         // 0..31
    const int cbase = warp_n * 32 + (lane & 3) * 2;     // even col of this lane

#pragma unroll
    for (int g = 0; g < 4; ++g) {
        float se = 0.f, so = 0.f, qe = 0.f, qo = 0.f;
#pragma unroll
        for (int f = 0; f < 2; ++f) {
            const float e0 = acc[f][g][0], e1 = acc[f][g][2];
            const float o0 = acc[f][g][1], o1 = acc[f][g][3];
            se += e0 + e1;  qe += e0 * e0 + e1 * e1;
            so += o0 + o1;  qo += o0 * o0 + o1 * o1;
        }
        Psum[prow * 128 + cbase + g * 8]     = se;
        Psum[prow * 128 + cbase + g * 8 + 1] = so;
        Psq [prow * 128 + cbase + g * 8]     = qe;
        Psq [prow * 128 + cbase + g * 8 + 1] = qo;
    }
    __syncthreads();

    if (tid < 128) {
        float s = 0.f, s2 = 0.f;
#pragma unroll
        for (int r = 0; r < 32; r++) {
            s  += Psum[r * 128 + tid];
            s2 += Psq [r * 128 + tid];
        }
        const float mean = s * (1.0f / 128.0f);
        const float var  = s2 * (1.0f / 128.0f) - mean * mean;
        const float sc   = gamma[n0 + tid] * rsqrtf(var + EPS_BN);
        cscale[tid] = sc;
        cshift[tid] = beta[n0 + tid] - mean * sc;
    }
    __syncthreads();

#pragma unroll
    for (int g = 0; g < 4; ++g) {
        const int cl = cbase + g * 8;
        const float2 sc = *(const float2*)&cscale[cl];
        const float2 sh = *(const float2*)&cshift[cl];
        const int col = n0 + cl;
#pragma unroll
        for (int f = 0; f < 2; ++f) {
            const int row0 = m0 + warp_m * 32 + f * 16 + (lane >> 2);
#pragma unroll
            for (int h = 0; h < 2; ++h) {
                const size_t row = (size_t)(row0 + h * 8);
                const float2 p = *(const float2*)&priors[row * D_G + col];
                float2 z;
                z.x = fmaf(acc[f][g][h * 2 + 0], sc.x, sh.x) * p.x;
                z.y = fmaf(acc[f][g][h * 2 + 1], sc.y, sh.y) * p.y;
                *(float2*)&g_z[row * D_G + col] = z;
            }
        }
    }
}

// ---------------------------------------------------------------------------
// Kernel 2: sparsemax per row (D=512), Michelot fixed point. Warp per row.
// float4 vectorized I/O + redux.sync for the support-size reduction.
// ---------------------------------------------------------------------------
__global__ __launch_bounds__(256)
void sparsemax_kernel(float* __restrict__ out)
{
    const int gw   = (blockIdx.x * blockDim.x + threadIdx.x) >> 5;
    const int lane = threadIdx.x & 31;
    const float4* zr = (const float4*)(g_z + (size_t)gw * D_G);

    float4 v[4];
#pragma unroll
    for (int c = 0; c < 4; c++) v[c] = zr[c * 32 + lane];

    float mx = fmaxf(fmaxf(v[0].x, v[0].y), fmaxf(v[0].z, v[0].w));
#pragma unroll
    for (int c = 1; c < 4; c++)
        mx = fmaxf(mx, fmaxf(fmaxf(v[c].x, v[c].y), fmaxf(v[c].z, v[c].w)));
#pragma unroll
    for (int o = 16; o > 0; o >>= 1)
        mx = fmaxf(mx, __shfl_xor_sync(0xffffffffu, mx, o));

    float s = 0.0f;
#pragma unroll
    for (int c = 0; c < 4; c++) {
        v[c].x -= mx; v[c].y -= mx; v[c].z -= mx; v[c].w -= mx;
        s += (v[c].x + v[c].y) + (v[c].z + v[c].w);
    }
#pragma unroll
    for (int o = 16; o > 0; o >>= 1)
        s += __shfl_xor_sync(0xffffffffu, s, o);

    float tau = (s - 1.0f) * (1.0f / 512.0f);

    for (int it = 0; it < 64; ++it) {
        float ns = 0.0f;
        unsigned k = 0;
#pragma unroll
        for (int c = 0; c < 4; c++) {
            if (v[c].x > tau) { ns += v[c].x; k++; }
            if (v[c].y > tau) { ns += v[c].y; k++; }
            if (v[c].z > tau) { ns += v[c].z; k++; }
            if (v[c].w > tau) { ns += v[c].w; k++; }
        }
#pragma unroll
        for (int o = 16; o > 0; o >>= 1)
            ns += __shfl_xor_sync(0xffffffffu, ns, o);
        k = __reduce_add_sync(0xffffffffu, k);

        const float nt = (ns - 1.0f) / (float)k;
        if (nt == tau) break;
        tau = nt;
    }

    float4* orow = (float4*)(out + (size_t)gw * D_G);
#pragma unroll
    for (int c = 0; c < 4; c++) {
        float4 r;
        r.x = fmaxf(v[c].x - tau, 0.0f);
        r.y = fmaxf(v[c].y - tau, 0.0f);
        r.z = fmaxf(v[c].z - tau, 0.0f);
        r.w = fmaxf(v[c].w - tau, 0.0f);
        orow[c * 32 + lane] = r;
    }
}

// ---------------------------------------------------------------------------
extern "C" void kernel_launch(void* const* d_in, const int* in_sizes, int n_in,
                              void* d_out, int out_size)
{
    const float* priors = (const float*)d_in[0];   // [B, 512]
    const float* feat   = (const float*)d_in[1];   // [B, 256]
    const float* W      = (const float*)d_in[2];   // [512, 256]
    const float* gamma  = (const float*)d_in[3];   // [512]
    const float* beta   = (const float*)d_in[4];   // [512]
    float* out = (float*)d_out;                    // [B, 512]

    cudaFuncSetAttribute(gemm_gbn_mma,
                         cudaFuncAttributeMaxDynamicSharedMemorySize, SMEM_TOTAL);

    dim3 grid1(D_G / 128, B_ROWS / 128);           // (4, 512)
    gemm_gbn_mma<<<grid1, 512, SMEM_TOTAL>>>(feat, W, priors, gamma, beta);

    sparsemax_kernel<<<(B_ROWS * 32) / 256, 256>>>(out);
}